// round 4
// baseline (speedup 1.0000x reference)
#include <cuda_runtime.h>
#include <cuda_bf16.h>

#define NN 512
#define TT 32
#define MMSG 31
#define EE 64
#define AA 64
#define NREL 201      // 200 relations + self-loop id 200
#define NTOK (NN*TT)  // 16384
#define PB 32         // tokens per projection chunk
#define CAP 1024      // max tokens per bin (self K-bin holds exactly 512)
#define CHUNKS 16

// ---- device scratch (no allocations allowed) ------------------------------
__device__ float g_self[NN * EE];
__device__ float g_q[NTOK * AA];
__device__ float g_k[NTOK * AA];
__device__ float g_v[NTOK * AA];
__device__ int   g_cur[2 * 256];
__device__ int   g_list[2 * 256 * CAP];

__device__ __forceinline__ void token_rels(int t, const int* mt, const int* rln,
                                           const int* rlm, int& rqv, int& rk) {
    int n = t >> 5, m = t & 31;
    if (m == 0) { rqv = rln[n]; rk = 200; }
    else { int i = n * MMSG + m - 1; rqv = rlm[i]; rk = mt[i]; }
}

// ---- 1. self projection + cursor zeroing ------------------------------------
__global__ __launch_bounds__(256) void k_self(const float* __restrict__ h,
                                              const float* __restrict__ W_self) {
    if (blockIdx.x == 0) {
        int i = threadIdx.x;
        g_cur[i] = 0; g_cur[256 + i] = 0;
    }
    __shared__ float Ws[EE * EE];
    __shared__ float hb[16][EE];
    const int tid = threadIdx.x;
    const int n0 = blockIdx.x * 16;
    for (int i = tid; i < EE * EE / 4; i += 256)
        ((float4*)Ws)[i] = ((const float4*)W_self)[i];
    for (int i = tid; i < 16 * EE / 4; i += 256)
        ((float4*)&hb[0][0])[i] = ((const float4*)(h + n0 * EE))[i];
    __syncthreads();
    const int a = tid & 63, ng = tid >> 6;
    #pragma unroll
    for (int s = 0; s < 4; s++) {
        const int nl = ng + s * 4;
        float acc = 0.f;
        #pragma unroll
        for (int e = 0; e < EE; e++) acc = fmaf(hb[nl][e], Ws[e * EE + a], acc);
        g_self[(n0 + nl) * EE + a] = acc;
    }
}

// ---- 2. scatter tokens into fixed-capacity bins ------------------------------
__global__ void k_scatter(const int* __restrict__ mt, const int* __restrict__ rln,
                          const int* __restrict__ rlm) {
    int t = blockIdx.x * 512 + threadIdx.x;
    int rqv, rk; token_rels(t, mt, rln, rlm, rqv, rk);
    int p0 = atomicAdd(&g_cur[rqv], 1);
    g_list[rqv * CAP + p0] = t;
    int p1 = atomicAdd(&g_cur[256 + rk], 1);
    g_list[(256 + rk) * CAP + p1] = t;
}

// ---- 3. bucketed relation projections ----------------------------------------
__global__ __launch_bounds__(128) void k_proj(const float* __restrict__ msg,
                                              const float* __restrict__ Q,
                                              const float* __restrict__ K,
                                              const float* __restrict__ V) {
    const bool isK = blockIdx.x >= NREL;
    const int  r   = isK ? blockIdx.x - NREL : blockIdx.x;
    const int  bin = (isK ? 256 : 0) + r;
    const int  cnt = g_cur[bin];
    if ((int)blockIdx.y * PB >= cnt) return;

    __shared__ float Ws1[EE * AA];
    __shared__ float Ws2[EE * AA];
    __shared__ float xb[EE][PB];
    __shared__ int   tlist[PB];

    const int tid = threadIdx.x;
    const int* __restrict__ list = g_list + bin * CAP;

    {
        const float4* w1 = (const float4*)((isK ? K : Q) + (size_t)r * EE * AA);
        for (int i = tid; i < EE * AA / 4; i += 128) ((float4*)Ws1)[i] = w1[i];
        if (!isK) {
            const float4* w2 = (const float4*)(V + (size_t)r * EE * AA);
            for (int i = tid; i < EE * AA / 4; i += 128) ((float4*)Ws2)[i] = w2[i];
        }
    }

    const int ag = tid & 15;
    const int tg = tid >> 4;

    for (int c = blockIdx.y; c * PB < cnt; c += gridDim.y) {
        const int p  = c * PB;
        const int np = min(PB, cnt - p);
        __syncthreads();
        {
            const int tt = tid >> 2, qq = tid & 3;
            const bool valid = tt < np;
            int tok = valid ? list[p + tt] : 0;
            if (qq == 0) tlist[tt] = tok;
            const int n = tok >> 5, m = tok & 31;
            const float* xp = (m == 0) ? (g_self + n * EE)
                                       : (msg + (size_t)(n * MMSG + m - 1) * EE);
            #pragma unroll
            for (int j = 0; j < 4; j++) {
                const int e = qq * 16 + j * 4;
                float4 xv = valid ? *(const float4*)(xp + e) : make_float4(0.f,0.f,0.f,0.f);
                xb[e + 0][tt] = xv.x; xb[e + 1][tt] = xv.y;
                xb[e + 2][tt] = xv.z; xb[e + 3][tt] = xv.w;
            }
        }
        __syncthreads();

        if (!isK) {
            float a1[4][4], a2[4][4];
            #pragma unroll
            for (int j = 0; j < 4; j++)
                #pragma unroll
                for (int i = 0; i < 4; i++) { a1[j][i] = 0.f; a2[j][i] = 0.f; }
            #pragma unroll 8
            for (int e = 0; e < EE; e++) {
                const float4 w1 = *(const float4*)(Ws1 + e * AA + (ag << 2));
                const float4 w2 = *(const float4*)(Ws2 + e * AA + (ag << 2));
                const float4 xt = *(const float4*)(&xb[e][tg << 2]);
                const float xv[4]  = {xt.x, xt.y, xt.z, xt.w};
                const float w1v[4] = {w1.x, w1.y, w1.z, w1.w};
                const float w2v[4] = {w2.x, w2.y, w2.z, w2.w};
                #pragma unroll
                for (int j = 0; j < 4; j++)
                    #pragma unroll
                    for (int i = 0; i < 4; i++) {
                        a1[j][i] = fmaf(xv[j], w1v[i], a1[j][i]);
                        a2[j][i] = fmaf(xv[j], w2v[i], a2[j][i]);
                    }
            }
            #pragma unroll
            for (int j = 0; j < 4; j++) {
                const int ts = (tg << 2) + j;
                if (ts < np) {
                    const int tok = tlist[ts];
                    *(float4*)(g_q + (size_t)tok * AA + (ag << 2)) =
                        make_float4(a1[j][0], a1[j][1], a1[j][2], a1[j][3]);
                    *(float4*)(g_v + (size_t)tok * AA + (ag << 2)) =
                        make_float4(a2[j][0], a2[j][1], a2[j][2], a2[j][3]);
                }
            }
        } else {
            float a1[4][4];
            #pragma unroll
            for (int j = 0; j < 4; j++)
                #pragma unroll
                for (int i = 0; i < 4; i++) a1[j][i] = 0.f;
            #pragma unroll 8
            for (int e = 0; e < EE; e++) {
                const float4 w1 = *(const float4*)(Ws1 + e * AA + (ag << 2));
                const float4 xt = *(const float4*)(&xb[e][tg << 2]);
                const float xv[4]  = {xt.x, xt.y, xt.z, xt.w};
                const float w1v[4] = {w1.x, w1.y, w1.z, w1.w};
                #pragma unroll
                for (int j = 0; j < 4; j++)
                    #pragma unroll
                    for (int i = 0; i < 4; i++)
                        a1[j][i] = fmaf(xv[j], w1v[i], a1[j][i]);
            }
            #pragma unroll
            for (int j = 0; j < 4; j++) {
                const int ts = (tg << 2) + j;
                if (ts < np) {
                    const int tok = tlist[ts];
                    *(float4*)(g_k + (size_t)tok * AA + (ag << 2)) =
                        make_float4(a1[j][0], a1[j][1], a1[j][2], a1[j][3]);
                }
            }
        }
    }
}

// ---- 4. attention + pooling + FFN: 256 threads/node, float4 LDS --------------
#define ROWSTRIDE (EE + 4)   // 68 floats = 272B, float4-aligned rows
__global__ __launch_bounds__(256) void k_attn(const float* __restrict__ ffn_w,
                                              const float* __restrict__ ffn_b,
                                              float* __restrict__ out) {
    const int n = blockIdx.x, tid = threadIdx.x;
    __shared__ float qs[TT * ROWSTRIDE];
    __shared__ float ks2[TT * ROWSTRIDE];
    __shared__ float vs2[TT * ROWSTRIDE];
    __shared__ float sc[TT][TT + 1];
    __shared__ float att0[TT];
    __shared__ float pooled[AA];

    // cooperative vector load: 512 float4 per array, 2 per thread per array
    const float4* gq = (const float4*)(g_q + (size_t)n * TT * AA);
    const float4* gk = (const float4*)(g_k + (size_t)n * TT * AA);
    const float4* gv = (const float4*)(g_v + (size_t)n * TT * AA);
    #pragma unroll
    for (int it = 0; it < 2; it++) {
        const int i = tid + it * 256;            // i in [0,512)
        const int row = i >> 4, c = (i & 15) << 2;
        const int so = row * ROWSTRIDE + c;
        *(float4*)(qs  + so) = gq[i];
        *(float4*)(ks2 + so) = gk[i];
        *(float4*)(vs2 + so) = gv[i];
    }
    __syncthreads();

    // scores: thread -> 1 q-row x 4 k-cols, float4 over e
    {
        const int qr = tid >> 3, kg = (tid & 7) << 2;
        float a0 = 0.f, a1 = 0.f, a2 = 0.f, a3 = 0.f;
        #pragma unroll
        for (int es = 0; es < 16; es++) {
            const float4 q4 = *(const float4*)(qs + qr * ROWSTRIDE + es * 4);
            const float4 k0 = *(const float4*)(ks2 + (kg + 0) * ROWSTRIDE + es * 4);
            const float4 k1 = *(const float4*)(ks2 + (kg + 1) * ROWSTRIDE + es * 4);
            const float4 k2 = *(const float4*)(ks2 + (kg + 2) * ROWSTRIDE + es * 4);
            const float4 k3 = *(const float4*)(ks2 + (kg + 3) * ROWSTRIDE + es * 4);
            a0 = fmaf(q4.x, k0.x, fmaf(q4.y, k0.y, fmaf(q4.z, k0.z, fmaf(q4.w, k0.w, a0))));
            a1 = fmaf(q4.x, k1.x, fmaf(q4.y, k1.y, fmaf(q4.z, k1.z, fmaf(q4.w, k1.w, a1))));
            a2 = fmaf(q4.x, k2.x, fmaf(q4.y, k2.y, fmaf(q4.z, k2.z, fmaf(q4.w, k2.w, a2))));
            a3 = fmaf(q4.x, k3.x, fmaf(q4.y, k3.y, fmaf(q4.z, k3.z, fmaf(q4.w, k3.w, a3))));
        }
        sc[qr][kg + 0] = a0 * 0.125f;
        sc[qr][kg + 1] = a1 * 0.125f;
        sc[qr][kg + 2] = a2 * 0.125f;
        sc[qr][kg + 3] = a3 * 0.125f;
    }
    __syncthreads();

    // softmax over QUERY axis per k-column; only row 0 weight needed
    if (tid < TT) {
        const int kc = tid;
        float mx = -1e30f;
        #pragma unroll
        for (int q = 0; q < TT; q++) mx = fmaxf(mx, sc[q][kc]);
        float s = 0.f;
        #pragma unroll
        for (int q = 0; q < TT; q++) s += __expf(sc[q][kc] - mx);
        att0[kc] = __expf(sc[0][kc] - mx) / s;
    }
    __syncthreads();

    // pooled[a] = sum_k att0[k]*v[k][a] : 128 threads, 2 partials each
    if (tid < 128) {
        const int a = tid & 63, half = tid >> 6;   // half in {0,1}
        float acc = 0.f;
        #pragma unroll
        for (int k = 0; k < 16; k++)
            acc = fmaf(att0[half * 16 + k], vs2[(half * 16 + k) * ROWSTRIDE + a], acc);
        if (half == 0) pooled[a] = acc;
        __syncwarp();
    }
    __syncthreads();
    if (tid >= 64 && tid < 128) {
        // add second half (written after first half via shared? do it atomically-free)
    }
    // combine halves safely: redo with single pass to avoid ordering hazards
    __syncthreads();
    if (tid < AA) {
        float acc = 0.f;
        #pragma unroll
        for (int k = 0; k < TT; k++)
            acc = fmaf(att0[k], vs2[k * ROWSTRIDE + tid], acc);
        pooled[tid] = acc;
    }
    __syncthreads();

    if (tid < EE) {
        float acc = ffn_b[tid];
        #pragma unroll
        for (int a = 0; a < AA; a++) acc = fmaf(pooled[a], ffn_w[a * EE + tid], acc);
        out[n * EE + tid] = acc;
    }
}

extern "C" void kernel_launch(void* const* d_in, const int* in_sizes, int n_in,
                              void* d_out, int out_size) {
    const float* h            = (const float*)d_in[0];
    const float* msg          = (const float*)d_in[1];
    const int*   msg_type     = (const int*)  d_in[2];
    const int*   r_label_node = (const int*)  d_in[3];
    const int*   r_label_msg  = (const int*)  d_in[4];
    const float* W_self       = (const float*)d_in[5];
    const float* Q            = (const float*)d_in[6];
    const float* K            = (const float*)d_in[7];
    const float* V            = (const float*)d_in[8];
    const float* ffn_w        = (const float*)d_in[9];
    const float* ffn_b        = (const float*)d_in[10];
    float* out = (float*)d_out;

    k_self<<<NN / 16, 256>>>(h, W_self);
    k_scatter<<<NTOK / 512, 512>>>(msg_type, r_label_node, r_label_msg);
    dim3 pg(2 * NREL, CHUNKS);
    k_proj<<<pg, 128>>>(msg, Q, K, V);
    k_attn<<<NN, 256>>>(ffn_w, ffn_b, out);
}

// round 6
// speedup vs baseline: 1.2421x; 1.2421x over previous
#include <cuda_runtime.h>
#include <cuda_bf16.h>

#define NN 512
#define TT 32
#define MMSG 31
#define EE 64
#define AA 64
#define NREL 201      // 200 relations + self-loop id 200
#define NTOK (NN*TT)  // 16384
#define PB 32         // tokens per projection chunk
#define CAP 1024      // max tokens per bin (self K-bin holds exactly 512)
#define CHUNKS 16

// ---- device scratch (no allocations allowed) ------------------------------
__device__ float g_self[NN * EE];
__device__ float g_q[NTOK * AA];
__device__ float g_k[NTOK * AA];
__device__ float g_v[NTOK * AA];
__device__ int   g_cur[2 * 256];
__device__ int   g_list[2 * 256 * CAP];

__device__ __forceinline__ void token_rels(int t, const int* mt, const int* rln,
                                           const int* rlm, int& rqv, int& rk) {
    int n = t >> 5, m = t & 31;
    if (m == 0) { rqv = rln[n]; rk = 200; }
    else { int i = n * MMSG + m - 1; rqv = rlm[i]; rk = mt[i]; }
}

// ---- 1. self projection + cursor zeroing ------------------------------------
__global__ __launch_bounds__(256) void k_self(const float* __restrict__ h,
                                              const float* __restrict__ W_self) {
    if (blockIdx.x == 0) {
        int i = threadIdx.x;
        g_cur[i] = 0; g_cur[256 + i] = 0;
    }
    __shared__ float Ws[EE * EE];
    __shared__ float hb[16][EE];
    const int tid = threadIdx.x;
    const int n0 = blockIdx.x * 16;
    for (int i = tid; i < EE * EE / 4; i += 256)
        ((float4*)Ws)[i] = ((const float4*)W_self)[i];
    for (int i = tid; i < 16 * EE / 4; i += 256)
        ((float4*)&hb[0][0])[i] = ((const float4*)(h + n0 * EE))[i];
    __syncthreads();
    const int a = tid & 63, ng = tid >> 6;
    #pragma unroll
    for (int s = 0; s < 4; s++) {
        const int nl = ng + s * 4;
        float acc = 0.f;
        #pragma unroll
        for (int e = 0; e < EE; e++) acc = fmaf(hb[nl][e], Ws[e * EE + a], acc);
        g_self[(n0 + nl) * EE + a] = acc;
    }
}

// ---- 2. scatter tokens into fixed-capacity bins ------------------------------
__global__ void k_scatter(const int* __restrict__ mt, const int* __restrict__ rln,
                          const int* __restrict__ rlm) {
    int t = blockIdx.x * 512 + threadIdx.x;
    int rqv, rk; token_rels(t, mt, rln, rlm, rqv, rk);
    int p0 = atomicAdd(&g_cur[rqv], 1);
    g_list[rqv * CAP + p0] = t;
    int p1 = atomicAdd(&g_cur[256 + rk], 1);
    g_list[(256 + rk) * CAP + p1] = t;
}

// ---- 3. bucketed relation projections ----------------------------------------
__global__ __launch_bounds__(128) void k_proj(const float* __restrict__ msg,
                                              const float* __restrict__ Q,
                                              const float* __restrict__ K,
                                              const float* __restrict__ V) {
    const bool isK = blockIdx.x >= NREL;
    const int  r   = isK ? blockIdx.x - NREL : blockIdx.x;
    const int  bin = (isK ? 256 : 0) + r;
    const int  cnt = g_cur[bin];
    if ((int)blockIdx.y * PB >= cnt) return;

    __shared__ float Ws1[EE * AA];
    __shared__ float Ws2[EE * AA];
    __shared__ float xb[EE][PB];
    __shared__ int   tlist[PB];

    const int tid = threadIdx.x;
    const int* __restrict__ list = g_list + bin * CAP;

    {
        const float4* w1 = (const float4*)((isK ? K : Q) + (size_t)r * EE * AA);
        for (int i = tid; i < EE * AA / 4; i += 128) ((float4*)Ws1)[i] = w1[i];
        if (!isK) {
            const float4* w2 = (const float4*)(V + (size_t)r * EE * AA);
            for (int i = tid; i < EE * AA / 4; i += 128) ((float4*)Ws2)[i] = w2[i];
        }
    }

    const int ag = tid & 15;
    const int tg = tid >> 4;

    for (int c = blockIdx.y; c * PB < cnt; c += gridDim.y) {
        const int p  = c * PB;
        const int np = min(PB, cnt - p);
        __syncthreads();
        {
            const int tt = tid >> 2, qq = tid & 3;
            const bool valid = tt < np;
            int tok = valid ? list[p + tt] : 0;
            if (qq == 0) tlist[tt] = tok;
            const int n = tok >> 5, m = tok & 31;
            const float* xp = (m == 0) ? (g_self + n * EE)
                                       : (msg + (size_t)(n * MMSG + m - 1) * EE);
            #pragma unroll
            for (int j = 0; j < 4; j++) {
                const int e = qq * 16 + j * 4;
                float4 xv = valid ? *(const float4*)(xp + e) : make_float4(0.f,0.f,0.f,0.f);
                xb[e + 0][tt] = xv.x; xb[e + 1][tt] = xv.y;
                xb[e + 2][tt] = xv.z; xb[e + 3][tt] = xv.w;
            }
        }
        __syncthreads();

        if (!isK) {
            float a1[4][4], a2[4][4];
            #pragma unroll
            for (int j = 0; j < 4; j++)
                #pragma unroll
                for (int i = 0; i < 4; i++) { a1[j][i] = 0.f; a2[j][i] = 0.f; }
            #pragma unroll 8
            for (int e = 0; e < EE; e++) {
                const float4 w1 = *(const float4*)(Ws1 + e * AA + (ag << 2));
                const float4 w2 = *(const float4*)(Ws2 + e * AA + (ag << 2));
                const float4 xt = *(const float4*)(&xb[e][tg << 2]);
                const float xv[4]  = {xt.x, xt.y, xt.z, xt.w};
                const float w1v[4] = {w1.x, w1.y, w1.z, w1.w};
                const float w2v[4] = {w2.x, w2.y, w2.z, w2.w};
                #pragma unroll
                for (int j = 0; j < 4; j++)
                    #pragma unroll
                    for (int i = 0; i < 4; i++) {
                        a1[j][i] = fmaf(xv[j], w1v[i], a1[j][i]);
                        a2[j][i] = fmaf(xv[j], w2v[i], a2[j][i]);
                    }
            }
            #pragma unroll
            for (int j = 0; j < 4; j++) {
                const int ts = (tg << 2) + j;
                if (ts < np) {
                    const int tok = tlist[ts];
                    *(float4*)(g_q + (size_t)tok * AA + (ag << 2)) =
                        make_float4(a1[j][0], a1[j][1], a1[j][2], a1[j][3]);
                    *(float4*)(g_v + (size_t)tok * AA + (ag << 2)) =
                        make_float4(a2[j][0], a2[j][1], a2[j][2], a2[j][3]);
                }
            }
        } else {
            float a1[4][4];
            #pragma unroll
            for (int j = 0; j < 4; j++)
                #pragma unroll
                for (int i = 0; i < 4; i++) a1[j][i] = 0.f;
            #pragma unroll 8
            for (int e = 0; e < EE; e++) {
                const float4 w1 = *(const float4*)(Ws1 + e * AA + (ag << 2));
                const float4 xt = *(const float4*)(&xb[e][tg << 2]);
                const float xv[4]  = {xt.x, xt.y, xt.z, xt.w};
                const float w1v[4] = {w1.x, w1.y, w1.z, w1.w};
                #pragma unroll
                for (int j = 0; j < 4; j++)
                    #pragma unroll
                    for (int i = 0; i < 4; i++)
                        a1[j][i] = fmaf(xv[j], w1v[i], a1[j][i]);
            }
            #pragma unroll
            for (int j = 0; j < 4; j++) {
                const int ts = (tg << 2) + j;
                if (ts < np) {
                    const int tok = tlist[ts];
                    *(float4*)(g_k + (size_t)tok * AA + (ag << 2)) =
                        make_float4(a1[j][0], a1[j][1], a1[j][2], a1[j][3]);
                }
            }
        }
    }
}

// ---- 4. attention + pooling + FFN --------------------------------------------
// 256 threads/node. QSTRIDE=68 floats = 272B (16B multiple -> STS.128 legal).
// K stored TRANSPOSED kT[e][kc], row stride 36 floats (144B, 16B multiple):
// score loop reads float4 at banks (4e + kc0)%32; the 8 kc0 lanes per warp
// cover all 32 banks -> conflict-free. q-read is 4 distinct broadcast addrs.
#define QSTRIDE 68
#define KTSTRIDE 36
struct __align__(16) AttnSmem {
    float qs[TT * QSTRIDE];
    float vs2[TT * QSTRIDE];
    float kT[EE * KTSTRIDE];
    float sc[TT][TT + 1];
    float att0[TT];
    float pooled[AA];
};
__global__ __launch_bounds__(256) void k_attn(const float* __restrict__ ffn_w,
                                              const float* __restrict__ ffn_b,
                                              float* __restrict__ out) {
    const int n = blockIdx.x, tid = threadIdx.x;
    __shared__ AttnSmem s;

    const float4* gq = (const float4*)(g_q + (size_t)n * TT * AA);
    const float4* gk = (const float4*)(g_k + (size_t)n * TT * AA);
    const float4* gv = (const float4*)(g_v + (size_t)n * TT * AA);

    // issue all 6 global loads first (MLP), then store to SMEM
    const int i0 = tid, i1 = tid + 256;          // each in [0,512)
    const float4 q0 = gq[i0], q1 = gq[i1];
    const float4 k0 = gk[i0], k1 = gk[i1];
    const float4 v0 = gv[i0], v1 = gv[i1];
    {
        const int r0 = i0 >> 4, c0 = (i0 & 15) << 2;
        const int r1 = i1 >> 4, c1 = (i1 & 15) << 2;
        *(float4*)(s.qs + r0 * QSTRIDE + c0) = q0;
        *(float4*)(s.qs + r1 * QSTRIDE + c1) = q1;
        *(float4*)(s.vs2 + r0 * QSTRIDE + c0) = v0;
        *(float4*)(s.vs2 + r1 * QSTRIDE + c1) = v1;
        // transposed k: kT[e][token]
        s.kT[(c0 + 0) * KTSTRIDE + r0] = k0.x;
        s.kT[(c0 + 1) * KTSTRIDE + r0] = k0.y;
        s.kT[(c0 + 2) * KTSTRIDE + r0] = k0.z;
        s.kT[(c0 + 3) * KTSTRIDE + r0] = k0.w;
        s.kT[(c1 + 0) * KTSTRIDE + r1] = k1.x;
        s.kT[(c1 + 1) * KTSTRIDE + r1] = k1.y;
        s.kT[(c1 + 2) * KTSTRIDE + r1] = k1.z;
        s.kT[(c1 + 3) * KTSTRIDE + r1] = k1.w;
    }
    __syncthreads();

    // scores: thread -> (q-row qr) x (4 k-cols kc0..kc0+3)
    {
        const int qr = tid >> 3, kc0 = (tid & 7) << 2;
        float a0 = 0.f, a1 = 0.f, a2 = 0.f, a3 = 0.f;
        #pragma unroll 16
        for (int e = 0; e < EE; e++) {
            const float qv = s.qs[qr * QSTRIDE + e];
            const float4 k4 = *(const float4*)(s.kT + e * KTSTRIDE + kc0);
            a0 = fmaf(qv, k4.x, a0);
            a1 = fmaf(qv, k4.y, a1);
            a2 = fmaf(qv, k4.z, a2);
            a3 = fmaf(qv, k4.w, a3);
        }
        s.sc[qr][kc0 + 0] = a0 * 0.125f;
        s.sc[qr][kc0 + 1] = a1 * 0.125f;
        s.sc[qr][kc0 + 2] = a2 * 0.125f;
        s.sc[qr][kc0 + 3] = a3 * 0.125f;
    }
    __syncthreads();

    // softmax over QUERY axis per k-column; only row-0 weight needed
    if (tid < TT) {
        const int kc = tid;
        float mx = -1e30f;
        #pragma unroll
        for (int q = 0; q < TT; q++) mx = fmaxf(mx, s.sc[q][kc]);
        float sum = 0.f;
        #pragma unroll
        for (int q = 0; q < TT; q++) sum += __expf(s.sc[q][kc] - mx);
        s.att0[kc] = __expf(s.sc[0][kc] - mx) / sum;
    }
    __syncthreads();

    if (tid < AA) {
        float acc = 0.f;
        #pragma unroll
        for (int k = 0; k < TT; k++)
            acc = fmaf(s.att0[k], s.vs2[k * QSTRIDE + tid], acc);
        s.pooled[tid] = acc;
    }
    __syncthreads();

    if (tid < EE) {
        float acc = ffn_b[tid];
        #pragma unroll
        for (int a = 0; a < AA; a++) acc = fmaf(s.pooled[a], ffn_w[a * EE + tid], acc);
        out[n * EE + tid] = acc;
    }
}

extern "C" void kernel_launch(void* const* d_in, const int* in_sizes, int n_in,
                              void* d_out, int out_size) {
    const float* h            = (const float*)d_in[0];
    const float* msg          = (const float*)d_in[1];
    const int*   msg_type     = (const int*)  d_in[2];
    const int*   r_label_node = (const int*)  d_in[3];
    const int*   r_label_msg  = (const int*)  d_in[4];
    const float* W_self       = (const float*)d_in[5];
    const float* Q            = (const float*)d_in[6];
    const float* K            = (const float*)d_in[7];
    const float* V            = (const float*)d_in[8];
    const float* ffn_w        = (const float*)d_in[9];
    const float* ffn_b        = (const float*)d_in[10];
    float* out = (float*)d_out;

    k_self<<<NN / 16, 256>>>(h, W_self);
    k_scatter<<<NTOK / 512, 512>>>(msg_type, r_label_node, r_label_msg);
    dim3 pg(2 * NREL, CHUNKS);
    k_proj<<<pg, 128>>>(msg, Q, K, V);
    k_attn<<<NN, 256>>>(ffn_w, ffn_b, out);
}

// round 7
// speedup vs baseline: 1.2955x; 1.0430x over previous
#include <cuda_runtime.h>
#include <cuda_bf16.h>

#define NN 512
#define TT 32
#define MMSG 31
#define EE 64
#define AA 64
#define NREL 201      // 200 relations + self-loop id 200
#define NTOK (NN*TT)  // 16384
#define PB 64         // tokens per projection chunk
#define CAP 1024      // max tokens per bin (self K-bin holds exactly 512)
#define CHUNKS 8      // 8*64 = 512 covers the largest bin

// ---- device scratch (no allocations allowed) ------------------------------
__device__ float g_self[NN * EE];
__device__ float g_q[NTOK * AA];
__device__ float g_k[NTOK * AA];
__device__ float g_v[NTOK * AA];
__device__ int   g_cur[2 * 256];       // zero-initialized at load; re-zeroed by k_attn
__device__ int   g_list[2 * 256 * CAP];

__device__ __forceinline__ void token_rels(int t, const int* mt, const int* rln,
                                           const int* rlm, int& rqv, int& rk) {
    int n = t >> 5, m = t & 31;
    if (m == 0) { rqv = rln[n]; rk = 200; }
    else { int i = n * MMSG + m - 1; rqv = rlm[i]; rk = mt[i]; }
}

// ---- 1. prep: scatter (blocks 0..63) + self projection (blocks 64..95) -------
// g_cur is zero on entry: static init covers launch #1; k_attn re-zeroes at the
// end of every launch thereafter (same stream => ordered).
__global__ __launch_bounds__(256) void k_prep(const float* __restrict__ h,
                                              const float* __restrict__ W_self,
                                              const int* __restrict__ mt,
                                              const int* __restrict__ rln,
                                              const int* __restrict__ rlm) {
    const int b = blockIdx.x, tid = threadIdx.x;
    if (b < 64) {
        const int t = b * 256 + tid;
        int rqv, rk; token_rels(t, mt, rln, rlm, rqv, rk);
        int p0 = atomicAdd(&g_cur[rqv], 1);
        g_list[rqv * CAP + p0] = t;
        int p1 = atomicAdd(&g_cur[256 + rk], 1);
        g_list[(256 + rk) * CAP + p1] = t;
        return;
    }
    __shared__ float Ws[EE * EE];
    __shared__ float hb[16][EE];
    const int n0 = (b - 64) * 16;
    for (int i = tid; i < EE * EE / 4; i += 256)
        ((float4*)Ws)[i] = ((const float4*)W_self)[i];
    for (int i = tid; i < 16 * EE / 4; i += 256)
        ((float4*)&hb[0][0])[i] = ((const float4*)(h + n0 * EE))[i];
    __syncthreads();
    const int a = tid & 63, ng = tid >> 6;
    #pragma unroll
    for (int s = 0; s < 4; s++) {
        const int nl = ng + s * 4;
        float acc = 0.f;
        #pragma unroll
        for (int e = 0; e < EE; e++) acc = fmaf(hb[nl][e], Ws[e * EE + a], acc);
        g_self[(n0 + nl) * EE + a] = acc;
    }
}

// ---- 2. bucketed relation projections: 256 thr, 64-token chunks ---------------
__global__ __launch_bounds__(256) void k_proj(const float* __restrict__ msg,
                                              const float* __restrict__ Q,
                                              const float* __restrict__ K,
                                              const float* __restrict__ V) {
    const bool isK = blockIdx.x >= NREL;
    const int  r   = isK ? blockIdx.x - NREL : blockIdx.x;
    const int  bin = (isK ? 256 : 0) + r;
    const int  cnt = g_cur[bin];
    if ((int)blockIdx.y * PB >= cnt) return;

    __shared__ float Ws1[EE * AA];   // 16 KB
    __shared__ float Ws2[EE * AA];   // 16 KB
    __shared__ float xb[EE][PB];     // 16 KB -> exactly 48 KB total

    const int tid = threadIdx.x;
    const int* __restrict__ list = g_list + bin * CAP;

    {
        const float4* w1 = (const float4*)((isK ? K : Q) + (size_t)r * EE * AA);
        #pragma unroll
        for (int i = tid; i < EE * AA / 4; i += 256) ((float4*)Ws1)[i] = w1[i];
        if (!isK) {
            const float4* w2 = (const float4*)(V + (size_t)r * EE * AA);
            #pragma unroll
            for (int i = tid; i < EE * AA / 4; i += 256) ((float4*)Ws2)[i] = w2[i];
        }
    }

    const int ag = tid & 15;    // a-col group: cols ag*4..+3
    const int tg = tid >> 4;    // token group: tokens tg*4..+3 (0..15 -> 64)

    for (int c = blockIdx.y; c * PB < cnt; c += gridDim.y) {
        const int p  = c * PB;
        const int np = min(PB, cnt - p);
        __syncthreads();
        {
            const int tt = tid >> 2, qq = tid & 3;    // tt 0..63
            const bool valid = tt < np;
            int tok = valid ? list[p + tt] : 0;
            const int n = tok >> 5, m = tok & 31;
            const float* xp = (m == 0) ? (g_self + n * EE)
                                       : (msg + (size_t)(n * MMSG + m - 1) * EE);
            #pragma unroll
            for (int j = 0; j < 4; j++) {
                const int e = qq * 16 + j * 4;
                float4 xv = valid ? *(const float4*)(xp + e) : make_float4(0.f,0.f,0.f,0.f);
                xb[e + 0][tt] = xv.x; xb[e + 1][tt] = xv.y;
                xb[e + 2][tt] = xv.z; xb[e + 3][tt] = xv.w;
            }
        }
        __syncthreads();

        if (!isK) {
            float a1[4][4], a2[4][4];
            #pragma unroll
            for (int j = 0; j < 4; j++)
                #pragma unroll
                for (int i = 0; i < 4; i++) { a1[j][i] = 0.f; a2[j][i] = 0.f; }
            #pragma unroll 8
            for (int e = 0; e < EE; e++) {
                const float4 w1 = *(const float4*)(Ws1 + e * AA + (ag << 2));
                const float4 w2 = *(const float4*)(Ws2 + e * AA + (ag << 2));
                const float4 xt = *(const float4*)(&xb[e][tg << 2]);
                const float xv[4]  = {xt.x, xt.y, xt.z, xt.w};
                const float w1v[4] = {w1.x, w1.y, w1.z, w1.w};
                const float w2v[4] = {w2.x, w2.y, w2.z, w2.w};
                #pragma unroll
                for (int j = 0; j < 4; j++)
                    #pragma unroll
                    for (int i = 0; i < 4; i++) {
                        a1[j][i] = fmaf(xv[j], w1v[i], a1[j][i]);
                        a2[j][i] = fmaf(xv[j], w2v[i], a2[j][i]);
                    }
            }
            #pragma unroll
            for (int j = 0; j < 4; j++) {
                const int ts = (tg << 2) + j;
                if (ts < np) {
                    const int tok = list[p + ts];
                    *(float4*)(g_q + (size_t)tok * AA + (ag << 2)) =
                        make_float4(a1[j][0], a1[j][1], a1[j][2], a1[j][3]);
                    *(float4*)(g_v + (size_t)tok * AA + (ag << 2)) =
                        make_float4(a2[j][0], a2[j][1], a2[j][2], a2[j][3]);
                }
            }
        } else {
            float a1[4][4];
            #pragma unroll
            for (int j = 0; j < 4; j++)
                #pragma unroll
                for (int i = 0; i < 4; i++) a1[j][i] = 0.f;
            #pragma unroll 8
            for (int e = 0; e < EE; e++) {
                const float4 w1 = *(const float4*)(Ws1 + e * AA + (ag << 2));
                const float4 xt = *(const float4*)(&xb[e][tg << 2]);
                const float xv[4]  = {xt.x, xt.y, xt.z, xt.w};
                const float w1v[4] = {w1.x, w1.y, w1.z, w1.w};
                #pragma unroll
                for (int j = 0; j < 4; j++)
                    #pragma unroll
                    for (int i = 0; i < 4; i++)
                        a1[j][i] = fmaf(xv[j], w1v[i], a1[j][i]);
            }
            #pragma unroll
            for (int j = 0; j < 4; j++) {
                const int ts = (tg << 2) + j;
                if (ts < np) {
                    const int tok = list[p + ts];
                    *(float4*)(g_k + (size_t)tok * AA + (ag << 2)) =
                        make_float4(a1[j][0], a1[j][1], a1[j][2], a1[j][3]);
                }
            }
        }
    }
}

// ---- 3. attention + pooling + FFN (proven R6 version) + cursor re-zero --------
#define QSTRIDE 68
#define KTSTRIDE 36
struct __align__(16) AttnSmem {
    float qs[TT * QSTRIDE];
    float vs2[TT * QSTRIDE];
    float kT[EE * KTSTRIDE];
    float sc[TT][TT + 1];
    float att0[TT];
    float pooled[AA];
};
__global__ __launch_bounds__(256) void k_attn(const float* __restrict__ ffn_w,
                                              const float* __restrict__ ffn_b,
                                              float* __restrict__ out) {
    const int n = blockIdx.x, tid = threadIdx.x;
    // leave cursors zeroed for the NEXT launch (replay-safe; nothing in this
    // launch reads g_cur after k_proj finished)
    if (n == 0) { g_cur[tid] = 0; g_cur[256 + tid] = 0; }
    __shared__ AttnSmem s;

    const float4* gq = (const float4*)(g_q + (size_t)n * TT * AA);
    const float4* gk = (const float4*)(g_k + (size_t)n * TT * AA);
    const float4* gv = (const float4*)(g_v + (size_t)n * TT * AA);

    const int i0 = tid, i1 = tid + 256;
    const float4 q0 = gq[i0], q1 = gq[i1];
    const float4 k0 = gk[i0], k1 = gk[i1];
    const float4 v0 = gv[i0], v1 = gv[i1];
    {
        const int r0 = i0 >> 4, c0 = (i0 & 15) << 2;
        const int r1 = i1 >> 4, c1 = (i1 & 15) << 2;
        *(float4*)(s.qs + r0 * QSTRIDE + c0) = q0;
        *(float4*)(s.qs + r1 * QSTRIDE + c1) = q1;
        *(float4*)(s.vs2 + r0 * QSTRIDE + c0) = v0;
        *(float4*)(s.vs2 + r1 * QSTRIDE + c1) = v1;
        s.kT[(c0 + 0) * KTSTRIDE + r0] = k0.x;
        s.kT[(c0 + 1) * KTSTRIDE + r0] = k0.y;
        s.kT[(c0 + 2) * KTSTRIDE + r0] = k0.z;
        s.kT[(c0 + 3) * KTSTRIDE + r0] = k0.w;
        s.kT[(c1 + 0) * KTSTRIDE + r1] = k1.x;
        s.kT[(c1 + 1) * KTSTRIDE + r1] = k1.y;
        s.kT[(c1 + 2) * KTSTRIDE + r1] = k1.z;
        s.kT[(c1 + 3) * KTSTRIDE + r1] = k1.w;
    }
    __syncthreads();

    {
        const int qr = tid >> 3, kc0 = (tid & 7) << 2;
        float a0 = 0.f, a1 = 0.f, a2 = 0.f, a3 = 0.f;
        #pragma unroll 16
        for (int e = 0; e < EE; e++) {
            const float qv = s.qs[qr * QSTRIDE + e];
            const float4 k4 = *(const float4*)(s.kT + e * KTSTRIDE + kc0);
            a0 = fmaf(qv, k4.x, a0);
            a1 = fmaf(qv, k4.y, a1);
            a2 = fmaf(qv, k4.z, a2);
            a3 = fmaf(qv, k4.w, a3);
        }
        s.sc[qr][kc0 + 0] = a0 * 0.125f;
        s.sc[qr][kc0 + 1] = a1 * 0.125f;
        s.sc[qr][kc0 + 2] = a2 * 0.125f;
        s.sc[qr][kc0 + 3] = a3 * 0.125f;
    }
    __syncthreads();

    if (tid < TT) {
        const int kc = tid;
        float mx = -1e30f;
        #pragma unroll
        for (int q = 0; q < TT; q++) mx = fmaxf(mx, s.sc[q][kc]);
        float sum = 0.f;
        #pragma unroll
        for (int q = 0; q < TT; q++) sum += __expf(s.sc[q][kc] - mx);
        s.att0[kc] = __expf(s.sc[0][kc] - mx) / sum;
    }
    __syncthreads();

    if (tid < AA) {
        float acc = 0.f;
        #pragma unroll
        for (int k = 0; k < TT; k++)
            acc = fmaf(s.att0[k], s.vs2[k * QSTRIDE + tid], acc);
        s.pooled[tid] = acc;
    }
    __syncthreads();

    if (tid < EE) {
        float acc = ffn_b[tid];
        #pragma unroll
        for (int a = 0; a < AA; a++) acc = fmaf(s.pooled[a], ffn_w[a * EE + tid], acc);
        out[n * EE + tid] = acc;
    }
}

extern "C" void kernel_launch(void* const* d_in, const int* in_sizes, int n_in,
                              void* d_out, int out_size) {
    const float* h            = (const float*)d_in[0];
    const float* msg          = (const float*)d_in[1];
    const int*   msg_type     = (const int*)  d_in[2];
    const int*   r_label_node = (const int*)  d_in[3];
    const int*   r_label_msg  = (const int*)  d_in[4];
    const float* W_self       = (const float*)d_in[5];
    const float* Q            = (const float*)d_in[6];
    const float* K            = (const float*)d_in[7];
    const float* V            = (const float*)d_in[8];
    const float* ffn_w        = (const float*)d_in[9];
    const float* ffn_b        = (const float*)d_in[10];
    float* out = (float*)d_out;

    k_prep<<<96, 256>>>(h, W_self, msg_type, r_label_node, r_label_msg);
    dim3 pg(2 * NREL, CHUNKS);
    k_proj<<<pg, 256>>>(msg, Q, K, V);
    k_attn<<<NN, 256>>>(ffn_w, ffn_b, out);
}

// round 8
// speedup vs baseline: 1.3035x; 1.0062x over previous
#include <cuda_runtime.h>
#include <cuda_bf16.h>

#define NN 512
#define TT 32
#define MMSG 31
#define EE 64
#define AA 64
#define NREL 201
#define NTOK (NN*TT)
#define PB 64
#define CAP 1024
#define CHUNKS 8
#define SELF_BIN (256 + 200)

// ---- device scratch ---------------------------------------------------------
__device__ float g_self[NN * EE];
__device__ float g_q[NTOK * AA];
__device__ float g_k[NTOK * AA];
__device__ float g_v[NTOK * AA];
__device__ int   g_cur[2 * 256];       // zeroed at load; re-zeroed by k_attn
__device__ int   g_list[2 * 256 * CAP];

// ---- 1. prep: zero-out + scatter (blocks 0..63) + self GEMM (64..95) ---------
__global__ __launch_bounds__(256) void k_prep(const float* __restrict__ h,
                                              const float* __restrict__ W_self,
                                              const int* __restrict__ mt,
                                              const int* __restrict__ rln,
                                              const int* __restrict__ rlm,
                                              float* __restrict__ out) {
    const int b = blockIdx.x, tid = threadIdx.x;
    if (b < 64) {
        // zero the output accumulator (8192 float4 over 64 blocks)
        if (tid < 128)
            ((float4*)out)[b * 128 + tid] = make_float4(0.f, 0.f, 0.f, 0.f);
        const int t = b * 256 + tid;
        const int n = t >> 5, m = t & 31;
        if (m == 0) {
            const int rqv = rln[n];
            int p0 = atomicAdd(&g_cur[rqv], 1);
            g_list[rqv * CAP + p0] = t;
            // self K-bin: deterministic slot, NO atomic (kills 512-way hotspot)
            g_list[SELF_BIN * CAP + n] = t;
        } else {
            const int i = n * MMSG + m - 1;
            const int rqv = rlm[i], rk = mt[i];
            int p0 = atomicAdd(&g_cur[rqv], 1);
            g_list[rqv * CAP + p0] = t;
            int p1 = atomicAdd(&g_cur[256 + rk], 1);
            g_list[(256 + rk) * CAP + p1] = t;
        }
        return;
    }
    if (b == 64 && tid == 0) g_cur[SELF_BIN] = NN;   // count known statically
    __shared__ float Ws[EE * EE];
    __shared__ float hb[16][EE];
    const int n0 = (b - 64) * 16;
    for (int i = tid; i < EE * EE / 4; i += 256)
        ((float4*)Ws)[i] = ((const float4*)W_self)[i];
    for (int i = tid; i < 16 * EE / 4; i += 256)
        ((float4*)&hb[0][0])[i] = ((const float4*)(h + n0 * EE))[i];
    __syncthreads();
    const int a = tid & 63, ng = tid >> 6;
    #pragma unroll
    for (int s = 0; s < 4; s++) {
        const int nl = ng + s * 4;
        float acc = 0.f;
        #pragma unroll
        for (int e = 0; e < EE; e++) acc = fmaf(hb[nl][e], Ws[e * EE + a], acc);
        g_self[(n0 + nl) * EE + a] = acc;
    }
}

// ---- 2. bucketed relation projections (proven R7 version) --------------------
__global__ __launch_bounds__(256) void k_proj(const float* __restrict__ msg,
                                              const float* __restrict__ Q,
                                              const float* __restrict__ K,
                                              const float* __restrict__ V) {
    const bool isK = blockIdx.x >= NREL;
    const int  r   = isK ? blockIdx.x - NREL : blockIdx.x;
    const int  bin = (isK ? 256 : 0) + r;
    const int  cnt = g_cur[bin];
    if ((int)blockIdx.y * PB >= cnt) return;

    __shared__ float Ws1[EE * AA];
    __shared__ float Ws2[EE * AA];
    __shared__ float xb[EE][PB];

    const int tid = threadIdx.x;
    const int* __restrict__ list = g_list + bin * CAP;

    {
        const float4* w1 = (const float4*)((isK ? K : Q) + (size_t)r * EE * AA);
        #pragma unroll
        for (int i = tid; i < EE * AA / 4; i += 256) ((float4*)Ws1)[i] = w1[i];
        if (!isK) {
            const float4* w2 = (const float4*)(V + (size_t)r * EE * AA);
            #pragma unroll
            for (int i = tid; i < EE * AA / 4; i += 256) ((float4*)Ws2)[i] = w2[i];
        }
    }

    const int ag = tid & 15;
    const int tg = tid >> 4;

    for (int c = blockIdx.y; c * PB < cnt; c += gridDim.y) {
        const int p  = c * PB;
        const int np = min(PB, cnt - p);
        __syncthreads();
        {
            const int tt = tid >> 2, qq = tid & 3;
            const bool valid = tt < np;
            int tok = valid ? list[p + tt] : 0;
            const int n = tok >> 5, m = tok & 31;
            const float* xp = (m == 0) ? (g_self + n * EE)
                                       : (msg + (size_t)(n * MMSG + m - 1) * EE);
            #pragma unroll
            for (int j = 0; j < 4; j++) {
                const int e = qq * 16 + j * 4;
                float4 xv = valid ? *(const float4*)(xp + e) : make_float4(0.f,0.f,0.f,0.f);
                xb[e + 0][tt] = xv.x; xb[e + 1][tt] = xv.y;
                xb[e + 2][tt] = xv.z; xb[e + 3][tt] = xv.w;
            }
        }
        __syncthreads();

        if (!isK) {
            float a1[4][4], a2[4][4];
            #pragma unroll
            for (int j = 0; j < 4; j++)
                #pragma unroll
                for (int i = 0; i < 4; i++) { a1[j][i] = 0.f; a2[j][i] = 0.f; }
            #pragma unroll 8
            for (int e = 0; e < EE; e++) {
                const float4 w1 = *(const float4*)(Ws1 + e * AA + (ag << 2));
                const float4 w2 = *(const float4*)(Ws2 + e * AA + (ag << 2));
                const float4 xt = *(const float4*)(&xb[e][tg << 2]);
                const float xv[4]  = {xt.x, xt.y, xt.z, xt.w};
                const float w1v[4] = {w1.x, w1.y, w1.z, w1.w};
                const float w2v[4] = {w2.x, w2.y, w2.z, w2.w};
                #pragma unroll
                for (int j = 0; j < 4; j++)
                    #pragma unroll
                    for (int i = 0; i < 4; i++) {
                        a1[j][i] = fmaf(xv[j], w1v[i], a1[j][i]);
                        a2[j][i] = fmaf(xv[j], w2v[i], a2[j][i]);
                    }
            }
            #pragma unroll
            for (int j = 0; j < 4; j++) {
                const int ts = (tg << 2) + j;
                if (ts < np) {
                    const int tok = list[p + ts];
                    *(float4*)(g_q + (size_t)tok * AA + (ag << 2)) =
                        make_float4(a1[j][0], a1[j][1], a1[j][2], a1[j][3]);
                    *(float4*)(g_v + (size_t)tok * AA + (ag << 2)) =
                        make_float4(a2[j][0], a2[j][1], a2[j][2], a2[j][3]);
                }
            }
        } else {
            float a1[4][4];
            #pragma unroll
            for (int j = 0; j < 4; j++)
                #pragma unroll
                for (int i = 0; i < 4; i++) a1[j][i] = 0.f;
            #pragma unroll 8
            for (int e = 0; e < EE; e++) {
                const float4 w1 = *(const float4*)(Ws1 + e * AA + (ag << 2));
                const float4 xt = *(const float4*)(&xb[e][tg << 2]);
                const float xv[4]  = {xt.x, xt.y, xt.z, xt.w};
                const float w1v[4] = {w1.x, w1.y, w1.z, w1.w};
                #pragma unroll
                for (int j = 0; j < 4; j++)
                    #pragma unroll
                    for (int i = 0; i < 4; i++)
                        a1[j][i] = fmaf(xv[j], w1v[i], a1[j][i]);
            }
            #pragma unroll
            for (int j = 0; j < 4; j++) {
                const int ts = (tg << 2) + j;
                if (ts < np) {
                    const int tok = list[p + ts];
                    *(float4*)(g_k + (size_t)tok * AA + (ag << 2)) =
                        make_float4(a1[j][0], a1[j][1], a1[j][2], a1[j][3]);
                }
            }
        }
    }
}

// ---- 3. attention split: 2 CTAs per node, 16 k-columns each -------------------
// column-softmax is independent per kc; out gets exactly 2 atomic float adds
// per element (commutative -> deterministic). out zeroed in k_prep.
#define KHALF 16
#define QST 68
#define KTST 18   // float2 rows, 8 lanes cover 16 banks, qr groups broadcast
struct __align__(16) Attn2Smem {
    float qs[TT * QST];
    float vs[KHALF * QST];
    float kT[EE * KTST];
    float sc[TT][KHALF + 1];
    float att0[KHALF];
    float pooled[AA];
};
__global__ __launch_bounds__(256) void k_attn(const float* __restrict__ ffn_w,
                                              const float* __restrict__ ffn_b,
                                              float* __restrict__ out) {
    const int n = blockIdx.x, half = blockIdx.y, tid = threadIdx.x;
    if (n == 0 && half == 0) { g_cur[tid] = 0; g_cur[256 + tid] = 0; }
    __shared__ Attn2Smem s;

    const float4* gq = (const float4*)(g_q + (size_t)n * TT * AA);
    const float4* gk = (const float4*)(g_k + (size_t)n * TT * AA + (size_t)half * KHALF * AA);
    const float4* gv = (const float4*)(g_v + (size_t)n * TT * AA + (size_t)half * KHALF * AA);

    // 4 independent LDG.128 per thread
    const int i1 = tid + 256;
    const float4 q0 = gq[tid], q1 = gq[i1];
    const float4 k0 = gk[tid];              // 16 rows x 16 f4 = 256
    const float4 v0 = gv[tid];
    {
        const int r0 = tid >> 4, c0 = (tid & 15) << 2;
        const int r1 = i1 >> 4, c1 = (i1 & 15) << 2;
        *(float4*)(s.qs + r0 * QST + c0) = q0;
        *(float4*)(s.qs + r1 * QST + c1) = q1;
        *(float4*)(s.vs + r0 * QST + c0) = v0;
        s.kT[(c0 + 0) * KTST + r0] = k0.x;
        s.kT[(c0 + 1) * KTST + r0] = k0.y;
        s.kT[(c0 + 2) * KTST + r0] = k0.z;
        s.kT[(c0 + 3) * KTST + r0] = k0.w;
    }
    __syncthreads();

    // scores: thread -> q-row (tid>>3) x 2 k-cols
    {
        const int qr = tid >> 3, kc0 = (tid & 7) << 1;
        float a0 = 0.f, a1 = 0.f;
        #pragma unroll 16
        for (int e = 0; e < EE; e++) {
            const float qv = s.qs[qr * QST + e];
            const float2 k2 = *(const float2*)(s.kT + e * KTST + kc0);
            a0 = fmaf(qv, k2.x, a0);
            a1 = fmaf(qv, k2.y, a1);
        }
        s.sc[qr][kc0 + 0] = a0 * 0.125f;
        s.sc[qr][kc0 + 1] = a1 * 0.125f;
    }
    __syncthreads();

    // softmax over the 32 QUERY rows for each of our 16 columns
    if (tid < KHALF) {
        const int kc = tid;
        float mx = -1e30f;
        #pragma unroll
        for (int q = 0; q < TT; q++) mx = fmaxf(mx, s.sc[q][kc]);
        float sum = 0.f;
        #pragma unroll
        for (int q = 0; q < TT; q++) sum += __expf(s.sc[q][kc] - mx);
        s.att0[kc] = __expf(s.sc[0][kc] - mx) / sum;
    }
    __syncthreads();

    // partial pool over our 16 k rows
    if (tid < AA) {
        float acc = 0.f;
        #pragma unroll
        for (int k = 0; k < KHALF; k++)
            acc = fmaf(s.att0[k], s.vs[k * QST + tid], acc);
        s.pooled[tid] = acc;
    }
    __syncthreads();

    // partial FFN contribution; bias added once (half 0)
    if (tid < EE) {
        float acc = (half == 0) ? ffn_b[tid] : 0.f;
        #pragma unroll
        for (int a = 0; a < AA; a++)
            acc = fmaf(s.pooled[a], ffn_w[a * EE + tid], acc);
        atomicAdd(&out[n * EE + tid], acc);
    }
}

extern "C" void kernel_launch(void* const* d_in, const int* in_sizes, int n_in,
                              void* d_out, int out_size) {
    const float* h            = (const float*)d_in[0];
    const float* msg          = (const float*)d_in[1];
    const int*   msg_type     = (const int*)  d_in[2];
    const int*   r_label_node = (const int*)  d_in[3];
    const int*   r_label_msg  = (const int*)  d_in[4];
    const float* W_self       = (const float*)d_in[5];
    const float* Q            = (const float*)d_in[6];
    const float* K            = (const float*)d_in[7];
    const float* V            = (const float*)d_in[8];
    const float* ffn_w        = (const float*)d_in[9];
    const float* ffn_b        = (const float*)d_in[10];
    float* out = (float*)d_out;

    k_prep<<<96, 256>>>(h, W_self, msg_type, r_label_node, r_label_msg, out);
    dim3 pg(2 * NREL, CHUNKS);
    k_proj<<<pg, 256>>>(msg, Q, K, V);
    dim3 ag(NN, 2);
    k_attn<<<ag, 256>>>(ffn_w, ffn_b, out);
}